// round 1
// baseline (speedup 1.0000x reference)
#include <cuda_runtime.h>

// FMFMNeuronInhib: T=1024 sequential LIF steps over B=16384 neurons.
// HBM-bound streaming scan: 128MB in, 128MB out.
// Strategy: one thread per neuron, register double-buffered prefetch of
// UNROLL=16 timesteps to keep ~2MB of loads in flight (512 warps total).

#define T_STEPS 1024
#define BATCH   16384
#define UNROLL  16
#define TPB     64

__global__ void __launch_bounds__(TPB, 1) fmfm_kernel(
    const float2* __restrict__ x,      // [T, B] pairs (x0, x1)
    const float*  __restrict__ w_exc,  // [2] = {0.7, 1.0}
    const float*  __restrict__ w_inh,  // [1] = {-1.0}
    float*        __restrict__ out)    // [2, T, B]: spk_rec then mem_rec
{
    const int b = blockIdx.x * TPB + threadIdx.x;

    const float w0 = __ldg(&w_exc[0]);
    const float w1 = __ldg(&w_exc[1]);
    const float wi = __ldg(&w_inh[0]);

    const float2* xp   = x + b;
    float*        spk  = out + b;
    float*        memo = out + (size_t)T_STEPS * BATCH + b;

    float mem = 0.0f;
    float inh = 0.0f;

    // Prologue: prefetch first UNROLL timesteps.
    float2 buf[UNROLL];
#pragma unroll
    for (int u = 0; u < UNROLL; u++)
        buf[u] = __ldcs(xp + (size_t)u * BATCH);

    for (int t = 0; t < T_STEPS; t += UNROLL) {
        // Consume current window into a second register set...
        float2 curw[UNROLL];
#pragma unroll
        for (int u = 0; u < UNROLL; u++)
            curw[u] = buf[u];

        // ...and immediately issue the next window's loads (independent of
        // the recurrence), so 16 DRAM loads/thread stay in flight while we
        // compute + store the current window.
        if (t + UNROLL < T_STEPS) {
            const float2* xn = xp + (size_t)(t + UNROLL) * BATCH;
#pragma unroll
            for (int u = 0; u < UNROLL; u++)
                buf[u] = __ldcs(xn + (size_t)u * BATCH);
        }

#pragma unroll
        for (int u = 0; u < UNROLL; u++) {
            const float x0 = curw[u].x;
            const float x1 = curw[u].y;

            // inh = 0.6*inh + x0
            inh = fmaf(0.6f, inh, x0);
            // cur = x0*w0 + x1*w1 + w_inh*inh
            float cur = fmaf(w0, x0, w1 * x1);
            cur = fmaf(wi, inh, cur);
            // reset from OLD mem (stop_gradient((mem - 1) > 0)), THRESHOLD=1
            const float reset = (mem > 1.0f) ? 1.0f : 0.0f;
            // mem = 0.9*mem + cur - reset
            mem = fmaf(0.9f, mem, cur - reset);
            // spk from NEW mem
            const float s = (mem > 1.0f) ? 1.0f : 0.0f;

            __stcs(spk  + (size_t)(t + u) * BATCH, s);
            __stcs(memo + (size_t)(t + u) * BATCH, mem);
        }
    }
}

extern "C" void kernel_launch(void* const* d_in, const int* in_sizes, int n_in,
                              void* d_out, int out_size) {
    const float* x     = (const float*)d_in[0];  // spike_seq [1024,16384,2]
    const float* w_exc = (const float*)d_in[1];  // [1,2]
    const float* w_inh = (const float*)d_in[2];  // scalar
    float* out = (float*)d_out;                  // [2,1024,16384]

    fmfm_kernel<<<BATCH / TPB, TPB>>>((const float2*)x, w_exc, w_inh, out);
}

// round 2
// speedup vs baseline: 1.1648x; 1.1648x over previous
#include <cuda_runtime.h>

// FMFMNeuronInhib: T=1024 sequential LIF steps over B=16384 neurons.
// Pure HBM stream (128MB in, 128MB out), parallelism capped at B threads.
// R2: depth-2 register prefetch pipeline. While computing window t, windows
// t+1 and t+2 are in flight (32 LDG.64/thread outstanding ~= 4MB chip-wide,
// above the ~1.7MB BW*latency product), with load issue interleaved into the
// compute loop to keep in-flight bytes flat instead of bursty.

#define T_STEPS 1024
#define BATCH   16384
#define UNROLL  16
#define TPB     64
#define STRIDE  ((size_t)BATCH)

template <bool PREFETCH>
__device__ __forceinline__ void step_window(
    float2* __restrict__ buf,          // consumed, then refilled from `pre`
    const float2* __restrict__ pre,    // source for window t+2 (if PREFETCH)
    float& mem, float& inh,
    float w0, float w1, float wi,
    float* __restrict__ spk, float* __restrict__ memo, int tbase)
{
#pragma unroll
    for (int u = 0; u < UNROLL; u++) {
        const float2 v = buf[u];
        if (PREFETCH)
            buf[u] = __ldcs(pre + (size_t)u * STRIDE);  // issue t+2 load now

        // inh = 0.6*inh + x0
        inh = fmaf(0.6f, inh, v.x);
        // cur = x0*w0 + x1*w1 + w_inh*inh
        float cur = fmaf(w0, v.x, w1 * v.y);
        cur = fmaf(wi, inh, cur);
        // reset computed from OLD mem; THRESHOLD = 1
        const float reset = (mem > 1.0f) ? 1.0f : 0.0f;
        // mem = 0.9*mem + cur - reset
        mem = fmaf(0.9f, mem, cur - reset);
        // spike from NEW mem
        const float s = (mem > 1.0f) ? 1.0f : 0.0f;

        __stcs(spk  + (size_t)(tbase + u) * STRIDE, s);
        __stcs(memo + (size_t)(tbase + u) * STRIDE, mem);
    }
}

__global__ void __launch_bounds__(TPB, 1) fmfm_kernel(
    const float2* __restrict__ x,      // [T, B] pairs (x0, x1)
    const float*  __restrict__ w_exc,  // [2] = {0.7, 1.0}
    const float*  __restrict__ w_inh,  // [1] = {-1.0}
    float*        __restrict__ out)    // [2, T, B]: spk_rec then mem_rec
{
    const int b = blockIdx.x * TPB + threadIdx.x;

    const float w0 = __ldg(&w_exc[0]);
    const float w1 = __ldg(&w_exc[1]);
    const float wi = __ldg(&w_inh[0]);

    const float2* xp   = x + b;
    float*        spk  = out + b;
    float*        memo = out + (size_t)T_STEPS * BATCH + b;

    float mem = 0.0f;
    float inh = 0.0f;

    // Prologue: prefetch windows 0 and 1 (32 loads in flight).
    float2 buf0[UNROLL], buf1[UNROLL];
#pragma unroll
    for (int u = 0; u < UNROLL; u++)
        buf0[u] = __ldcs(xp + (size_t)u * STRIDE);
#pragma unroll
    for (int u = 0; u < UNROLL; u++)
        buf1[u] = __ldcs(xp + (size_t)(UNROLL + u) * STRIDE);

    // Steady state: consume window t while refilling its buffer with t+2.
    int t = 0;
    for (; t < T_STEPS - 2 * UNROLL; t += 2 * UNROLL) {
        step_window<true>(buf0, xp + (size_t)(t + 2 * UNROLL) * STRIDE,
                          mem, inh, w0, w1, wi, spk, memo, t);
        step_window<true>(buf1, xp + (size_t)(t + 3 * UNROLL) * STRIDE,
                          mem, inh, w0, w1, wi, spk, memo, t + UNROLL);
    }
    // Epilogue: last two windows, nothing left to prefetch.
    step_window<false>(buf0, nullptr, mem, inh, w0, w1, wi, spk, memo, t);
    step_window<false>(buf1, nullptr, mem, inh, w0, w1, wi, spk, memo, t + UNROLL);
}

extern "C" void kernel_launch(void* const* d_in, const int* in_sizes, int n_in,
                              void* d_out, int out_size) {
    const float* x     = (const float*)d_in[0];  // spike_seq [1024,16384,2]
    const float* w_exc = (const float*)d_in[1];  // [1,2]
    const float* w_inh = (const float*)d_in[2];  // scalar
    float* out = (float*)d_out;                  // [2,1024,16384]

    fmfm_kernel<<<BATCH / TPB, TPB>>>((const float2*)x, w_exc, w_inh, out);
}

// round 3
// speedup vs baseline: 1.3107x; 1.1252x over previous
#include <cuda_runtime.h>

// FMFMNeuronInhib: T=1024 LIF steps over B=16384 neurons. HBM stream.
// R3: chunked-restart scan. The recurrence forgets exponentially (mem x0.9,
// inh x0.6 per step), so split T into 4 chunks of 256; each block recomputes
// its initial state via 192 discarded warm-up steps (0.9^192 ~ 1.6e-9).
// Parallelism x4 (2048 warps, ~14/SM). Warm-up re-reads hit L2 because the
// neighboring chunk's main read of the same region trails by 256 steps
// (32MB window << 126MB L2). Streaming stores keep output out of L2.

#define T_STEPS 1024
#define BATCH   16384
#define CHUNK   256
#define WARM    192
#define U       8
#define TPB     128
#define NCHUNK  (T_STEPS / CHUNK)
#define STRIDE  ((size_t)BATCH)

template <bool STORE, bool PREFETCH>
__device__ __forceinline__ void win(
    float2* __restrict__ buf,        // consumed; refilled from `pre` if PREFETCH
    const float2* __restrict__ pre,  // absolute src of window t+2U
    float& mem, float& inh,
    float w0, float w1, float wi,
    float* __restrict__ spk, float* __restrict__ memo, int tbase)
{
#pragma unroll
    for (int u = 0; u < U; u++) {
        const float2 v = buf[u];
        if (PREFETCH)
            buf[u] = __ldg(pre + (size_t)u * STRIDE);  // keep depth-2 in flight

        // inh = 0.6*inh + x0
        inh = fmaf(0.6f, inh, v.x);
        // cur = 0.7*x0 + 1.0*x1 + w_inh*inh
        float cur = fmaf(w0, v.x, w1 * v.y);
        cur = fmaf(wi, inh, cur);
        // reset from OLD mem (threshold 1), then mem = 0.9*mem + cur - reset
        const float reset = (mem > 1.0f) ? 1.0f : 0.0f;
        mem = fmaf(0.9f, mem, cur - reset);

        if (STORE) {
            const float s = (mem > 1.0f) ? 1.0f : 0.0f;
            __stcs(spk  + (size_t)(tbase + u) * STRIDE, s);
            __stcs(memo + (size_t)(tbase + u) * STRIDE, mem);
        }
    }
}

__global__ void __launch_bounds__(TPB, 1) fmfm_kernel(
    const float2* __restrict__ x,      // [T, B] pairs (x0, x1)
    const float*  __restrict__ w_exc,  // [2] = {0.7, 1.0}
    const float*  __restrict__ w_inh,  // [1] = {-1.0}
    float*        __restrict__ out)    // [2, T, B]: spk_rec then mem_rec
{
    const int nb    = BATCH / TPB;                       // blocks per chunk
    const int chunk = blockIdx.x / nb;
    const int b     = (blockIdx.x % nb) * TPB + threadIdx.x;

    const float w0 = __ldg(&w_exc[0]);
    const float w1 = __ldg(&w_exc[1]);
    const float wi = __ldg(&w_inh[0]);

    const int cs = chunk * CHUNK;          // first stored timestep
    const int ce = cs + CHUNK;             // one past last
    const int t0 = (chunk == 0) ? 0 : cs - WARM;

    const float2* xb   = x + b;
    float*        spk  = out + b;
    float*        memo = out + (size_t)T_STEPS * BATCH + b;

    float mem = 0.0f;
    float inh = 0.0f;

    // Prologue: prefetch windows t0 and t0+U.
    float2 buf0[U], buf1[U];
#pragma unroll
    for (int u = 0; u < U; u++)
        buf0[u] = __ldg(xb + (size_t)(t0 + u) * STRIDE);
#pragma unroll
    for (int u = 0; u < U; u++)
        buf1[u] = __ldg(xb + (size_t)(t0 + U + u) * STRIDE);

    int t = t0;
    // Warm-up: advance state, no stores (empty for chunk 0).
    for (; t < cs; t += 2 * U) {
        win<false, true>(buf0, xb + (size_t)(t + 2 * U) * STRIDE,
                         mem, inh, w0, w1, wi, spk, memo, t);
        win<false, true>(buf1, xb + (size_t)(t + 3 * U) * STRIDE,
                         mem, inh, w0, w1, wi, spk, memo, t + U);
    }
    // Main: store outputs, keep prefetching while data remains.
    for (; t < ce - 2 * U; t += 2 * U) {
        win<true, true>(buf0, xb + (size_t)(t + 2 * U) * STRIDE,
                        mem, inh, w0, w1, wi, spk, memo, t);
        win<true, true>(buf1, xb + (size_t)(t + 3 * U) * STRIDE,
                        mem, inh, w0, w1, wi, spk, memo, t + U);
    }
    // Epilogue: last two windows.
    win<true, false>(buf0, nullptr, mem, inh, w0, w1, wi, spk, memo, t);
    win<true, false>(buf1, nullptr, mem, inh, w0, w1, wi, spk, memo, t + U);
}

extern "C" void kernel_launch(void* const* d_in, const int* in_sizes, int n_in,
                              void* d_out, int out_size) {
    const float* x     = (const float*)d_in[0];  // spike_seq [1024,16384,2]
    const float* w_exc = (const float*)d_in[1];  // [1,2]
    const float* w_inh = (const float*)d_in[2];  // scalar
    float* out = (float*)d_out;                  // [2,1024,16384]

    fmfm_kernel<<<(BATCH / TPB) * NCHUNK, TPB>>>((const float2*)x, w_exc, w_inh, out);
}